// round 12
// baseline (speedup 1.0000x reference)
#include <cuda_runtime.h>
#include <math.h>

// Block floating-point quantization (block_size=16, mantissa_bits=8).
// FINAL (best measured: kernel 73.70us, DRAM 82.2%, 6509 GB/s):
// one-shot grid; 4 consecutive lanes share one 16-elem block (one float4
// each) -> every LDG.128/STG.128 fully warp-coalesced (512B/warp).
// 6 front-batched streaming loads per thread (MLP_p1=6, ~288 loads in
// flight per SM at ~62% occupancy). Measured at the GB300 HBM read+write
// bus ceiling (~6.5 TB/s, 81-82% of 8TB/s spec) across the full structural
// sweep (MLP 1-8, v4/v8, persistent/one-shot, blocked/interleaved layouts).

#define TPB 256
#define CHUNKS 6
#define TILE (TPB * CHUNKS)   // 1536 float4 per CTA

__device__ __forceinline__ float absmax4(float4 v) {
    return fmaxf(fmaxf(fabsf(v.x), fabsf(v.y)), fmaxf(fabsf(v.z), fabsf(v.w)));
}

__device__ __forceinline__ int bfp_exp(float a) {
    // floor(log2(a)) for a>0; a==0 -> 0 (all-zero block quantizes to 0 anyway).
    // Denormal block max (exp field 0, a>0) via ilogbf — practically unreachable.
    int ef = (__float_as_int(a) >> 23) & 0xFF;
    return (ef != 0) ? (ef - 127) : ((a > 0.0f) ? ilogbf(a) : 0);
}

__device__ __forceinline__ float4 bfp_quant(float4 v, int e) {
    int eb = e - 7;   // mantissa_bits - 1 = 7
    float s  = __int_as_float((eb + 127) << 23);   // 2^(e-7)
    float is = __int_as_float((127 - eb) << 23);   // 2^(7-e)
    float4 r;
    r.x = fminf(fmaxf(rintf(v.x * is), -128.0f), 127.0f) * s;
    r.y = fminf(fmaxf(rintf(v.y * is), -128.0f), 127.0f) * s;
    r.z = fminf(fmaxf(rintf(v.z * is), -128.0f), 127.0f) * s;
    r.w = fminf(fmaxf(rintf(v.w * is), -128.0f), 127.0f) * s;
    return r;
}

__global__ __launch_bounds__(TPB, 6) void bfp_quant_kernel(
    const float4* __restrict__ in, float4* __restrict__ out, int n4)
{
    int base = blockIdx.x * TILE + threadIdx.x;

    if (base + (CHUNKS - 1) * TPB < n4) {
        // ---- full-tile fast path: branch-free, 6 front-batched loads ----
        float4 v[CHUNKS];
        #pragma unroll
        for (int c = 0; c < CHUNKS; c++) v[c] = __ldcs(in + base + c * TPB);

        float a[CHUNKS];
        #pragma unroll
        for (int c = 0; c < CHUNKS; c++) a[c] = absmax4(v[c]);
        #pragma unroll
        for (int c = 0; c < CHUNKS; c++) a[c] = fmaxf(a[c], __shfl_xor_sync(0xffffffffu, a[c], 1));
        #pragma unroll
        for (int c = 0; c < CHUNKS; c++) a[c] = fmaxf(a[c], __shfl_xor_sync(0xffffffffu, a[c], 2));

        #pragma unroll
        for (int c = 0; c < CHUNKS; c++)
            __stcs(out + base + c * TPB, bfp_quant(v[c], bfp_exp(a[c])));
    } else {
        // ---- tail path (last CTA only) ----
        #pragma unroll
        for (int c = 0; c < CHUNKS; c++) {
            int i = base + c * TPB;
            bool pred = i < n4;
            float4 v = pred ? __ldcs(in + i) : make_float4(0.f, 0.f, 0.f, 0.f);
            float a = absmax4(v);
            a = fmaxf(a, __shfl_xor_sync(0xffffffffu, a, 1));
            a = fmaxf(a, __shfl_xor_sync(0xffffffffu, a, 2));
            if (pred) __stcs(out + i, bfp_quant(v, bfp_exp(a)));
        }
    }
}

extern "C" void kernel_launch(void* const* d_in, const int* in_sizes, int n_in,
                              void* d_out, int out_size)
{
    const float4* x = (const float4*)d_in[0];
    float4* out = (float4*)d_out;
    int n = in_sizes[0];           // 4*4096*4096 = 67108864
    int n4 = n / 4;                // 16777216 float4
    int blocks = (n4 + TILE - 1) / TILE;   // 10923
    bfp_quant_kernel<<<blocks, TPB>>>(x, out, n4);
}

// round 13
// speedup vs baseline: 1.0039x; 1.0039x over previous
#include <cuda_runtime.h>
#include <math.h>

// Block floating-point quantization (block_size=16, mantissa_bits=8).
// R10 best-measured config (kernel 73.70us, DRAM 82.2%) with one change:
// loads use ld.global.lu (last-use) instead of ld.global.cs — read-once
// lines are dropped from cache immediately after the read, freeing L2
// capacity for the outgoing write stream.
// One-shot grid; 4 consecutive lanes share one 16-elem block (one float4
// each) -> every LDG.128/STG.128 fully warp-coalesced (512B/warp);
// 6 front-batched loads per thread (MLP_p1=6).

#define TPB 256
#define CHUNKS 6
#define TILE (TPB * CHUNKS)   // 1536 float4 per CTA

__device__ __forceinline__ float4 ld128_lu(const float4* p) {
    float4 v;
    asm("ld.global.lu.v4.f32 {%0,%1,%2,%3}, [%4];"
        : "=f"(v.x), "=f"(v.y), "=f"(v.z), "=f"(v.w)
        : "l"(p));
    return v;
}

__device__ __forceinline__ float absmax4(float4 v) {
    return fmaxf(fmaxf(fabsf(v.x), fabsf(v.y)), fmaxf(fabsf(v.z), fabsf(v.w)));
}

__device__ __forceinline__ int bfp_exp(float a) {
    // floor(log2(a)) for a>0; a==0 -> 0 (all-zero block quantizes to 0 anyway).
    // Denormal block max (exp field 0, a>0) via ilogbf — practically unreachable.
    int ef = (__float_as_int(a) >> 23) & 0xFF;
    return (ef != 0) ? (ef - 127) : ((a > 0.0f) ? ilogbf(a) : 0);
}

__device__ __forceinline__ float4 bfp_quant(float4 v, int e) {
    int eb = e - 7;   // mantissa_bits - 1 = 7
    float s  = __int_as_float((eb + 127) << 23);   // 2^(e-7)
    float is = __int_as_float((127 - eb) << 23);   // 2^(7-e)
    float4 r;
    r.x = fminf(fmaxf(rintf(v.x * is), -128.0f), 127.0f) * s;
    r.y = fminf(fmaxf(rintf(v.y * is), -128.0f), 127.0f) * s;
    r.z = fminf(fmaxf(rintf(v.z * is), -128.0f), 127.0f) * s;
    r.w = fminf(fmaxf(rintf(v.w * is), -128.0f), 127.0f) * s;
    return r;
}

__global__ __launch_bounds__(TPB, 6) void bfp_quant_kernel(
    const float4* __restrict__ in, float4* __restrict__ out, int n4)
{
    int base = blockIdx.x * TILE + threadIdx.x;

    if (base + (CHUNKS - 1) * TPB < n4) {
        // ---- full-tile fast path: branch-free, 6 front-batched loads ----
        float4 v[CHUNKS];
        #pragma unroll
        for (int c = 0; c < CHUNKS; c++) v[c] = ld128_lu(in + base + c * TPB);

        float a[CHUNKS];
        #pragma unroll
        for (int c = 0; c < CHUNKS; c++) a[c] = absmax4(v[c]);
        #pragma unroll
        for (int c = 0; c < CHUNKS; c++) a[c] = fmaxf(a[c], __shfl_xor_sync(0xffffffffu, a[c], 1));
        #pragma unroll
        for (int c = 0; c < CHUNKS; c++) a[c] = fmaxf(a[c], __shfl_xor_sync(0xffffffffu, a[c], 2));

        #pragma unroll
        for (int c = 0; c < CHUNKS; c++)
            __stcs(out + base + c * TPB, bfp_quant(v[c], bfp_exp(a[c])));
    } else {
        // ---- tail path (last CTA only) ----
        #pragma unroll
        for (int c = 0; c < CHUNKS; c++) {
            int i = base + c * TPB;
            bool pred = i < n4;
            float4 v = pred ? ld128_lu(in + i) : make_float4(0.f, 0.f, 0.f, 0.f);
            float a = absmax4(v);
            a = fmaxf(a, __shfl_xor_sync(0xffffffffu, a, 1));
            a = fmaxf(a, __shfl_xor_sync(0xffffffffu, a, 2));
            if (pred) __stcs(out + i, bfp_quant(v, bfp_exp(a)));
        }
    }
}

extern "C" void kernel_launch(void* const* d_in, const int* in_sizes, int n_in,
                              void* d_out, int out_size)
{
    const float4* x = (const float4*)d_in[0];
    float4* out = (float4*)d_out;
    int n = in_sizes[0];           // 4*4096*4096 = 67108864
    int n4 = n / 4;                // 16777216 float4
    int blocks = (n4 + TILE - 1) / TILE;   // 10923
    bfp_quant_kernel<<<blocks, TPB>>>(x, out, n4);
}